// round 17
// baseline (speedup 1.0000x reference)
#include <cuda_runtime.h>
#include <cuda_bf16.h>
#include <math.h>

#define Bb 16
#define Cc 256
#define Tt 8192
#define KSPLIT 2
#define SL (Bb*Cc*Cc)
#define OUT_ELEMS ((size_t)Bb*Cc*Tt)

typedef unsigned long long u64;

// ---------------- scratch (static device globals; no allocation) -------------
__device__ float g_covp[(size_t)KSPLIT*SL];
__device__ float g_rs[Bb*Cc];
__device__ float g_diag[Bb*Cc];
__device__ float g_q[Bb*Cc*32];
__device__ float g_k[Bb*Cc*32];
__device__ __nv_bfloat16 g_xh[(size_t)Bb*Cc*Tt];      // x hi bf16 (written by cov diag tiles)
__device__ __nv_bfloat16 g_xl[(size_t)Bb*Cc*Tt];      // x lo bf16
__device__ __nv_bfloat16 g_attn_h[(size_t)Bb*Cc*Cc];  // attn hi [b][c][d]
__device__ __nv_bfloat16 g_attn_l[(size_t)Bb*Cc*Cc];  // attn lo [b][c][d]

// ---------------- mma.sync helpers (sm_80+ ISA) ------------------------------
__device__ __forceinline__ unsigned smem_u32(const void* p){
    unsigned a; asm("{ .reg .u64 t; cvta.to.shared.u64 t, %1; cvt.u32.u64 %0, t; }" : "=r"(a) : "l"(p)); return a;
}
__device__ __forceinline__ void cpasync16(unsigned dst, const void* src){
    asm volatile("cp.async.cg.shared.global [%0], [%1], 16;" :: "r"(dst), "l"(src));
}
__device__ __forceinline__ void ldsm_x4(unsigned* r, unsigned addr){
    asm volatile("ldmatrix.sync.aligned.m8n8.x4.shared.b16 {%0,%1,%2,%3}, [%4];"
        : "=r"(r[0]), "=r"(r[1]), "=r"(r[2]), "=r"(r[3]) : "r"(addr));
}
__device__ __forceinline__ void ldsm_x4_t(unsigned* r, unsigned addr){
    asm volatile("ldmatrix.sync.aligned.m8n8.x4.trans.shared.b16 {%0,%1,%2,%3}, [%4];"
        : "=r"(r[0]), "=r"(r[1]), "=r"(r[2]), "=r"(r[3]) : "r"(addr));
}
__device__ __forceinline__ void mma_bf16(float* d, const unsigned* a, const unsigned* b){
    asm volatile("mma.sync.aligned.m16n8k16.row.col.f32.bf16.bf16.f32 "
        "{%0,%1,%2,%3}, {%4,%5,%6,%7}, {%8,%9}, {%0,%1,%2,%3};"
        : "+f"(d[0]), "+f"(d[1]), "+f"(d[2]), "+f"(d[3])
        : "r"(a[0]), "r"(a[1]), "r"(a[2]), "r"(a[3]), "r"(b[0]), "r"(b[1]));
}
// pack 8 floats -> uint4 hi bf16 + uint4 lo bf16
__device__ __forceinline__ void pack8(const float* v, uint4& hi, uint4& lo){
    unsigned hw[4], lw[4];
    #pragma unroll
    for(int i=0;i<4;i++){
        __nv_bfloat16 h0 = __float2bfloat16(v[2*i]);
        __nv_bfloat16 h1 = __float2bfloat16(v[2*i+1]);
        __nv_bfloat16 l0 = __float2bfloat16(v[2*i]   - __bfloat162float(h0));
        __nv_bfloat16 l1 = __float2bfloat16(v[2*i+1] - __bfloat162float(h1));
        hw[i] = (unsigned)__bfloat16_as_ushort(h0) | ((unsigned)__bfloat16_as_ushort(h1)<<16);
        lw[i] = (unsigned)__bfloat16_as_ushort(l0) | ((unsigned)__bfloat16_as_ushort(l1)<<16);
    }
    hi = make_uint4(hw[0],hw[1],hw[2],hw[3]);
    lo = make_uint4(lw[0],lw[1],lw[2],lw[3]);
}

// =============================================================================
// K2: G = X X^T partials via mma.sync bf16x3, fp32 staging + in-kernel convert.
// Diag tiles (t0 rows 0-127, t2 rows 128-255) write converted bf16 hi/lo back
// to g_xh/g_xl — every x element exactly once across the 2 K-slices.
// SMEM: stage 2 x (A+B fp32, 272B rows) = 139264 + conv tiles 73728 = 212992.
// =============================================================================
__constant__ int t2_i[3]={0,0,1};
__constant__ int t2_j[3]={0,1,1};

#define CV_ST    34816                 // one fp32 stage operand: 128 x 272B
#define CV_STBUF (2*CV_ST)             // A + B
#define CV_TB    18432                 // one bf16 conv tile: 128 x 144B
#define CV_CONV  (4*CV_TB)             // AH AL BH BL
#define CV_SMEM  (2*CV_STBUF + CV_CONV)

__device__ __forceinline__ void cov_issue(unsigned sb, int buf, int kg, int i0, int j0,
                                          bool diag, int tid, const float* xb){
    unsigned dst = sb + buf*CV_STBUF;
    #pragma unroll
    for(int p=0;p<8;p++){                    // A: 128 rows x 16 float4
        int lin = p*256 + tid;
        int r = lin>>4, u = lin&15;
        cpasync16(dst + r*272 + u*16, &xb[(size_t)(i0+r)*Tt + kg + u*4]);
    }
    if(!diag){
        #pragma unroll
        for(int p=0;p<8;p++){
            int lin = p*256 + tid;
            int r = lin>>4, u = lin&15;
            cpasync16(dst + CV_ST + r*272 + u*16, &xb[(size_t)(j0+r)*Tt + kg + u*4]);
        }
    }
    asm volatile("cp.async.commit_group;" ::: "memory");
}

__global__ void __launch_bounds__(256) cov_mma(const float* __restrict__ x){
    extern __shared__ char sm[];
    unsigned sb = smem_u32(sm);
    float* smf = (float*)sm;
    int tid = threadIdx.x, w = tid>>5, lane = tid&31;
    int tile = blockIdx.x, b = blockIdx.y, sl = blockIdx.z;
    int i0 = t2_i[tile]*128, j0 = t2_j[tile]*128;
    bool diag = (i0==j0);
    int wc = w&3, wt = w>>2;
    const float* xb = x + (size_t)b*Cc*Tt;
    int kbase = sl*(Tt/KSPLIT);
    const int NCH = (Tt/KSPLIT)/64;          // 64
    unsigned conv = sb + 2*CV_STBUF;

    float acc[2][8][4];
    #pragma unroll
    for(int i=0;i<2;i++)
        #pragma unroll
        for(int j=0;j<8;j++)
            #pragma unroll
            for(int r=0;r<4;r++) acc[i][j][r]=0.f;

    cov_issue(sb, 0, kbase,    i0, j0, diag, tid, xb);
    cov_issue(sb, 1, kbase+64, i0, j0, diag, tid, xb);

    int cr = tid>>1, chf = tid&1;            // convert mapping: row, col-half

    #pragma unroll 1
    for(int ch=0; ch<NCH; ++ch){
        int buf = ch&1;
        if(ch==NCH-1) asm volatile("cp.async.wait_group 0;" ::: "memory");
        else          asm volatile("cp.async.wait_group 1;" ::: "memory");
        __syncthreads();                     // stage ready; prev MMA/writeback done with conv

        // ---- convert stage[buf] -> conv tiles (A always, B if off-diag) ----
        {
            const float* srow = smf + (buf*CV_STBUF)/4 + cr*68 + chf*32;
            #pragma unroll
            for(int j=0;j<4;j++){
                float v[8];
                *(float4*)&v[0] = *(const float4*)&srow[j*8];
                *(float4*)&v[4] = *(const float4*)&srow[j*8+4];
                uint4 hi, lo; pack8(v, hi, lo);
                *(uint4*)(sm + (conv-sb) + cr*144 + chf*64 + j*16)         = hi;
                *(uint4*)(sm + (conv-sb) + CV_TB + cr*144 + chf*64 + j*16) = lo;
            }
            if(!diag){
                const float* srb = srow + CV_ST/4;
                #pragma unroll
                for(int j=0;j<4;j++){
                    float v[8];
                    *(float4*)&v[0] = *(const float4*)&srb[j*8];
                    *(float4*)&v[4] = *(const float4*)&srb[j*8+4];
                    uint4 hi, lo; pack8(v, hi, lo);
                    *(uint4*)(sm + (conv-sb) + 2*CV_TB + cr*144 + chf*64 + j*16) = hi;
                    *(uint4*)(sm + (conv-sb) + 3*CV_TB + cr*144 + chf*64 + j*16) = lo;
                }
            }
        }
        __syncthreads();                     // conv tiles complete; stage[buf] free
        if(ch+2<NCH) cov_issue(sb, buf, kbase + (ch+2)*64, i0, j0, diag, tid, xb);

        // ---- diag tiles write converted A back to g_xh/g_xl ----
        if(diag){
            int kg = kbase + ch*64;
            #pragma unroll
            for(int p=0;p<8;p++){
                int lin = p*256 + tid;       // 2048 uint4 (hi + lo)
                int arr = lin>>10, r = (lin>>3)&127, u = lin&7;
                uint4 v = *(const uint4*)(sm + (conv-sb) + arr*CV_TB + r*144 + u*16);
                __nv_bfloat16* dstg = (arr ? g_xl : g_xh) + (size_t)b*Cc*Tt + (size_t)(i0+r)*Tt + kg + u*8;
                *(uint4*)dstg = v;
            }
        }

        // ---- MMA on conv tiles ----
        unsigned abase = conv;
        unsigned bbase = conv + (diag ? 0u : 2u*CV_TB);
        #pragma unroll
        for(int ks=0; ks<4; ks++){
            unsigned afh[2][4], afl[2][4];
            #pragma unroll
            for(int mt=0; mt<2; mt++){
                unsigned ra = abase + (unsigned)(wc*32 + mt*16 + (lane&15))*144
                            + ((lane>>4)<<4) + ks*32;
                ldsm_x4(afh[mt], ra);
                ldsm_x4(afl[mt], ra + CV_TB);
            }
            #pragma unroll
            for(int ng=0; ng<4; ng++){
                unsigned bfh[4], bfl[4];
                unsigned rb = bbase + (unsigned)(wt*64 + ng*16 + ((lane>>4)<<3) + (lane&7))*144
                            + (((lane>>3)&1)<<4) + ks*32;
                ldsm_x4(bfh, rb);
                ldsm_x4(bfl, rb + CV_TB);
                #pragma unroll
                for(int mt=0; mt<2; mt++){
                    mma_bf16(acc[mt][ng*2  ], afh[mt], &bfh[0]);
                    mma_bf16(acc[mt][ng*2  ], afh[mt], &bfl[0]);
                    mma_bf16(acc[mt][ng*2  ], afl[mt], &bfh[0]);
                    mma_bf16(acc[mt][ng*2+1], afh[mt], &bfh[2]);
                    mma_bf16(acc[mt][ng*2+1], afh[mt], &bfl[2]);
                    mma_bf16(acc[mt][ng*2+1], afl[mt], &bfh[2]);
                }
            }
        }
    }

    float* cp = g_covp + ((size_t)sl*Bb + b)*Cc*Cc;
    #pragma unroll
    for(int mt=0; mt<2; mt++){
        int r0 = i0 + wc*32 + mt*16 + (lane>>2);
        #pragma unroll
        for(int nt=0; nt<8; nt++){
            int co = j0 + wt*64 + nt*8 + (lane&3)*2;
            *(float2*)&cp[(size_t)r0*Cc + co]     = make_float2(acc[mt][nt][0], acc[mt][nt][1]);
            *(float2*)&cp[(size_t)(r0+8)*Cc + co] = make_float2(acc[mt][nt][2], acc[mt][nt][3]);
            if(!diag){
                cp[(size_t)co*Cc + r0]       = acc[mt][nt][0];
                cp[(size_t)(co+1)*Cc + r0]   = acc[mt][nt][1];
                cp[(size_t)co*Cc + r0+8]     = acc[mt][nt][2];
                cp[(size_t)(co+1)*Cc + r0+8] = acc[mt][nt][3];
            }
        }
    }
}

// =============================================================================
// K2b: row sums + diagonal of G (2 slices). grid (Bb, 8). (EXACT R16)
// =============================================================================
__global__ void __launch_bounds__(256) rowsum_kernel(){
    int b = blockIdx.x, rg = blockIdx.y;
    int tid = threadIdx.x, w = tid>>5, lane = tid&31;
    #pragma unroll
    for(int pass=0; pass<4; pass++){
        int r = rg*32 + pass*8 + w;
        float s = 0.f;
        #pragma unroll
        for(int sl=0; sl<KSPLIT; sl++){
            const float* rp = g_covp + ((size_t)sl*Bb + b)*Cc*Cc + (size_t)r*Cc;
            #pragma unroll
            for(int j=0;j<8;j++) s += rp[j*32 + lane];
        }
        #pragma unroll
        for(int d=16; d>0; d>>=1) s += __shfl_xor_sync(0xffffffffu, s, d);
        if(lane==0){
            g_rs[b*Cc+r]=s;
            float dv = 0.f;
            #pragma unroll
            for(int sl=0; sl<KSPLIT; sl++)
                dv += g_covp[((size_t)sl*Bb + b)*Cc*Cc + (size_t)r*Cc + r];
            g_diag[b*Cc+r]=dv;
        }
    }
}

// =============================================================================
// K3: pcc rows + q/k projections (EXACT R16)
// =============================================================================
#define PQ_WS   (256*65)
#define PQ_PR   (32*260)
#define PQ_SMEM ((PQ_WS + PQ_PR + 512)*4)

__global__ void __launch_bounds__(256) pccqk_kernel(const float* __restrict__ qw, const float* __restrict__ qb,
                                                    const float* __restrict__ kw, const float* __restrict__ kb){
    extern __shared__ float sdyn[];
    float* ws   = sdyn;
    float* prow = ws + PQ_WS;
    float* srs  = prow + PQ_PR;
    float* sdg  = srs + 256;
    __shared__ float sden, sSc;
    int tid = threadIdx.x;
    int cg = blockIdx.x, b = blockIdx.y;
    int c0 = cg*32;

    srs[tid] = g_rs[b*Cc + tid] * (1.0f/Cc);
    sdg[tid] = g_diag[b*Cc + tid];
    #pragma unroll
    for(int p=0;p<64;p++){
        int idx = p*256 + tid;
        int e = idx>>8, d = idx&255;
        float v = (e<32) ? qw[e*Cc+d] : kw[(e-32)*Cc+d];
        ws[d*65 + ((e&7)<<3) + (e>>3)] = v;
    }
    if(tid==0){
        float S=0.f, tr=0.f;
        #pragma unroll 8
        for(int i=0;i<Cc;i++){ S += srs[i]; tr += sdg[i]; }
        sSc = S*(1.0f/Cc);
        sden = (float)(Cc-1)/(tr - S);
    }
    __syncthreads();

    float Sc = sSc, den = sden;
    #pragma unroll
    for(int p=0;p<8;p++){
        int idx = p*256 + tid;
        int r = idx>>6, d4 = (idx&63)*4;
        size_t off = ((size_t)(c0+r))*Cc + (size_t)b*Cc*Cc + d4;
        float4 v0 = *(const float4*)&g_covp[off];
        float4 v1 = *(const float4*)&g_covp[(size_t)SL + off];
        float rc = srs[c0+r] - Sc;
        prow[r*260 + d4+0] = (v0.x+v1.x - rc - srs[d4+0])*den;
        prow[r*260 + d4+1] = (v0.y+v1.y - rc - srs[d4+1])*den;
        prow[r*260 + d4+2] = (v0.z+v1.z - rc - srs[d4+2])*den;
        prow[r*260 + d4+3] = (v0.w+v1.w - rc - srs[d4+3])*den;
    }
    __syncthreads();

    int r = tid>>3, g = tid&7;
    float acc[8];
    #pragma unroll
    for(int j=0;j<8;j++){
        int e = g*8 + j;
        acc[j] = (e<32) ? qb[e] : kb[e-32];
    }
    const float* pr = &prow[r*260];
    #pragma unroll 4
    for(int d=0; d<Cc; d++){
        float pv = pr[d];
        const float* wd = &ws[d*65 + g];
        #pragma unroll
        for(int j=0;j<8;j++) acc[j] += pv * wd[j*8];
    }
    int c = c0 + r;
    if(g<4){
        float* qp = &g_q[((size_t)b*Cc + c)*32 + g*8];
        *(float4*)&qp[0] = make_float4(acc[0],acc[1],acc[2],acc[3]);
        *(float4*)&qp[4] = make_float4(acc[4],acc[5],acc[6],acc[7]);
    }else{
        float* kp = &g_k[((size_t)b*Cc + c)*32 + (g-4)*8];
        *(float4*)&kp[0] = make_float4(acc[0],acc[1],acc[2],acc[3]);
        *(float4*)&kp[4] = make_float4(acc[4],acc[5],acc[6],acc[7]);
    }
}

// =============================================================================
// K4: scores + softmax, warp-per-query (EXACT R16)
// =============================================================================
__global__ void __launch_bounds__(256) attn_kernel(float* __restrict__ out){
    int bg = blockIdx.x, b = blockIdx.y;
    int tid = threadIdx.x, w = tid>>5, lane = tid&31;
    __shared__ float ks[256][36];
    __shared__ float qs[32][36];
    const float* kp = g_k + (size_t)b*Cc*32;
    int c0 = bg*32;
    #pragma unroll
    for(int p=0;p<8;p++){
        int idx = tid + p*256;
        int d = idx>>3, e4 = (idx&7)*4;
        *(float4*)&ks[d][e4] = *(const float4*)&kp[d*32 + e4];
    }
    {
        int q = tid>>3, e4 = (tid&7)*4;
        *(float4*)&qs[q][e4] = *(const float4*)&g_q[((size_t)b*Cc + c0 + q)*32 + e4];
    }
    __syncthreads();
    float* ao = out + OUT_ELEMS + ((size_t)b*Cc + c0)*Cc;
    #pragma unroll
    for(int qi=0; qi<4; qi++){
        int q = w*4 + qi;
        float s[8];
        #pragma unroll
        for(int m=0;m<8;m++) s[m]=0.f;
        #pragma unroll
        for(int e4=0;e4<8;e4++){
            float4 qv = *(const float4*)&qs[q][e4*4];
            #pragma unroll
            for(int m=0;m<8;m++){
                float4 kv = *(const float4*)&ks[m*32+lane][e4*4];
                s[m] += qv.x*kv.x + qv.y*kv.y + qv.z*kv.z + qv.w*kv.w;
            }
        }
        float mx = s[0]*(1.0f/16.0f);
        #pragma unroll
        for(int m=0;m<8;m++){ s[m] *= (1.0f/16.0f); mx = fmaxf(mx, s[m]); }
        #pragma unroll
        for(int d=16; d>0; d>>=1) mx = fmaxf(mx, __shfl_xor_sync(0xffffffffu, mx, d));
        float ev[8], sm=0.f;
        #pragma unroll
        for(int m=0;m<8;m++){ ev[m] = expf(s[m]-mx); sm += ev[m]; }
        #pragma unroll
        for(int d=16; d>0; d>>=1) sm += __shfl_xor_sync(0xffffffffu, sm, d);
        float inv = 1.0f/sm;
        #pragma unroll
        for(int m=0;m<8;m++){
            float a = ev[m]*inv;
            size_t idx = ((size_t)b*Cc + c0 + q)*Cc + m*32 + lane;
            ao[(size_t)q*Cc + m*32 + lane] = a;
            __nv_bfloat16 h = __float2bfloat16(a);
            g_attn_h[idx] = h;
            g_attn_l[idx] = __float2bfloat16(a - __bfloat162float(h));
        }
    }
}

// =============================================================================
// K5: out = attn @ x, c-supertile (EXACT R16 — known-good)
// =============================================================================
#define O2_AL   36864
#define O2_B    73728
#define O2_BL   17408
#define O2_BUF  108544
#define O2_SMEM (2*O2_BUF)

__device__ __forceinline__ void og2_issue(unsigned sb, int buf, int d0, int t0,
                                          int tid,
                                          const __nv_bfloat16* ah, const __nv_bfloat16* al,
                                          const __nv_bfloat16* xh, const __nv_bfloat16* xl){
    unsigned dst = sb + buf*O2_BUF;
    #pragma unroll
    for(int p=0;p<16;p++){
        int lin = p*256 + tid;
        int arr = lin>>11, r = (lin>>3)&255, u = lin&7;
        const __nv_bfloat16* s = (arr ? al : ah) + (size_t)r*Cc + d0 + u*8;
        cpasync16(dst + arr*O2_AL + r*144 + u*16, s);
    }
    #pragma unroll
    for(int p=0;p<8;p++){
        int lin = p*256 + tid;
        int arr = lin>>10, la = lin&1023;
        int r = la>>4, u = la&15;
        const __nv_bfloat16* s = (arr ? xl : xh) + (size_t)(d0+r)*Tt + t0 + u*8;
        cpasync16(dst + O2_B + arr*O2_BL + r*272 + u*16, s);
    }
    asm volatile("cp.async.commit_group;" ::: "memory");
}

__global__ void __launch_bounds__(256) out_gemm_mma(float* __restrict__ out){
    extern __shared__ char sm[];
    unsigned sb = smem_u32(sm);
    int tid = threadIdx.x, w = tid>>5, lane = tid&31;
    int t0 = blockIdx.x*128, b = blockIdx.y;
    const __nv_bfloat16* xh = g_xh + (size_t)b*Cc*Tt;
    const __nv_bfloat16* xl = g_xl + (size_t)b*Cc*Tt;
    const __nv_bfloat16* ah = g_attn_h + (size_t)b*Cc*Cc;
    const __nv_bfloat16* al = g_attn_l + (size_t)b*Cc*Cc;
    int wc = w&3, wt = w>>2;

    float acc[4][8][4];
    #pragma unroll
    for(int i=0;i<4;i++)
        #pragma unroll
        for(int j=0;j<8;j++)
            #pragma unroll
            for(int r=0;r<4;r++) acc[i][j][r]=0.f;

    og2_issue(sb, 0, 0,  t0, tid, ah, al, xh, xl);
    og2_issue(sb, 1, 64, t0, tid, ah, al, xh, xl);

    #pragma unroll 1
    for(int ch=0; ch<4; ++ch){
        int buf = ch&1;
        if(ch==3) asm volatile("cp.async.wait_group 0;" ::: "memory");
        else      asm volatile("cp.async.wait_group 1;" ::: "memory");
        __syncthreads();
        unsigned abase = sb + buf*O2_BUF;
        unsigned bbase = abase + O2_B;
        #pragma unroll
        for(int ks=0; ks<4; ks++){
            int k0 = ks*16;
            unsigned bfh[4][4], bfl[4][4];
            int kk = k0 + (lane&7) + (((lane>>3)&1)<<3);
            #pragma unroll
            for(int ng=0; ng<4; ng++){
                int tt = wt*64 + ng*16 + (((lane>>4)&1)<<3);
                unsigned rb = bbase + (unsigned)kk*272 + tt*2;
                ldsm_x4_t(bfh[ng], rb);
                ldsm_x4_t(bfl[ng], rb + O2_BL);
            }
            #pragma unroll
            for(int mt=0; mt<4; mt++){
                unsigned afh[4], afl[4];
                unsigned ra = abase + (unsigned)(wc*64 + mt*16 + (lane&15))*144
                            + k0*2 + ((lane>>4)<<4);
                ldsm_x4(afh, ra);
                ldsm_x4(afl, ra + O2_AL);
                #pragma unroll
                for(int ng=0; ng<4; ng++){
                    mma_bf16(acc[mt][ng*2  ], afh, &bfh[ng][0]);
                    mma_bf16(acc[mt][ng*2  ], afh, &bfl[ng][0]);
                    mma_bf16(acc[mt][ng*2  ], afl, &bfh[ng][0]);
                    mma_bf16(acc[mt][ng*2+1], afh, &bfh[ng][2]);
                    mma_bf16(acc[mt][ng*2+1], afh, &bfl[ng][2]);
                    mma_bf16(acc[mt][ng*2+1], afl, &bfh[ng][2]);
                }
            }
        }
        __syncthreads();
        if(ch+2<4) og2_issue(sb, buf, (ch+2)*64, t0, tid, ah, al, xh, xl);
    }

    float* ob = out + (size_t)b*Cc*Tt;
    #pragma unroll
    for(int mt=0; mt<4; mt++){
        int r0 = wc*64 + mt*16 + (lane>>2);
        #pragma unroll
        for(int nt=0; nt<8; nt++){
            int t = t0 + wt*64 + nt*8 + (lane&3)*2;
            *(float2*)&ob[(size_t)r0*Tt + t]     = make_float2(acc[mt][nt][0], acc[mt][nt][1]);
            *(float2*)&ob[(size_t)(r0+8)*Tt + t] = make_float2(acc[mt][nt][2], acc[mt][nt][3]);
        }
    }
}

// =============================================================================
extern "C" void kernel_launch(void* const* d_in, const int* in_sizes, int n_in,
                              void* d_out, int out_size){
    const float* x  = (const float*)d_in[0];
    const float* qw = (const float*)d_in[1];
    const float* qb = (const float*)d_in[2];
    const float* kw = (const float*)d_in[3];
    const float* kb = (const float*)d_in[4];
    float* out = (float*)d_out;

    cudaFuncSetAttribute(out_gemm_mma, cudaFuncAttributeMaxDynamicSharedMemorySize, O2_SMEM);
    cudaFuncSetAttribute(cov_mma, cudaFuncAttributeMaxDynamicSharedMemorySize, CV_SMEM);
    cudaFuncSetAttribute(pccqk_kernel, cudaFuncAttributeMaxDynamicSharedMemorySize, PQ_SMEM);

    cov_mma      <<<dim3(3, Bb, KSPLIT), 256, CV_SMEM>>>(x);
    rowsum_kernel<<<dim3(Bb, 8), 256>>>();
    pccqk_kernel <<<dim3(8, Bb), 256, PQ_SMEM>>>(qw, qb, kw, kb);
    attn_kernel  <<<dim3(Cc/32, Bb), 256>>>(out);
    out_gemm_mma <<<dim3(Tt/128, Bb), 256, O2_SMEM>>>(out);
}